// round 17
// baseline (speedup 1.0000x reference)
#include <cuda_runtime.h>
#include <cuda_fp16.h>
#include <cuda_bf16.h>
#include <cstdint>

// Problem constants (fixed shapes for TopKSAE_128849019036)
#define N_TOK   4096
#define D_MODEL 2048
#define D_SAE   32768
#define KTOP    64

// ---------------------------------------------------------------------------
// Device-global scratch (sanctioned; no dynamic allocation).
// Scaled fp16x2 split operands:
//   g_XA0 = fl16(x),  g_XA1 = fl16((x - fl16(x)) * 2^11)
//   g_WB0 = fl16(w),  g_WB1 = fl16((w - fl16(w)) * 2^11)      (w transposed)
// 2^11 scaling keeps the W residual in fp16 NORMAL range (the R14/R15
// failure was deterministic subnormal quantization of that residual).
// ---------------------------------------------------------------------------
__device__ __half g_XA0[(size_t)N_TOK * D_MODEL];
__device__ __half g_XA1[(size_t)N_TOK * D_MODEL];
__device__ __half g_WB0[(size_t)D_SAE * D_MODEL];
__device__ __half g_WB1[(size_t)D_SAE * D_MODEL];
__device__ float g_vals[N_TOK * KTOP];
__device__ int   g_idx [N_TOK * KTOP];

#define RSCALE     2048.0f           // 2^11
#define RSCALE_INV 4.8828125e-4f     // exact 2^-11

__device__ __forceinline__ uint32_t smem_u32(const void* p) {
    uint32_t a;
    asm("{ .reg .u64 t; cvta.to.shared.u64 t, %1; cvt.u32.u64 %0, t; }"
        : "=r"(a) : "l"(p));
    return a;
}

// scaled 2-way fp16 split: v = h0 + h1*2^-11 + O(~2e-8), h1 normal-range
__device__ __forceinline__ void split2s(float v, unsigned short& h0,
                                        unsigned short& h1) {
    __half a = __float2half_rn(v);
    float r = __fmul_rn(__fsub_rn(v, __half2float(a)), RSCALE);
    __half b = __float2half_rn(r);
    h0 = *reinterpret_cast<unsigned short*>(&a);
    h1 = *reinterpret_cast<unsigned short*>(&b);
}

// ===========================================================================
// Pre-pass 1: split x -> g_XA0/1 (same [M,K] layout)
// ===========================================================================
__global__ __launch_bounds__(256)
void split_x_kernel(const float* __restrict__ x)
{
    size_t gid = (size_t)blockIdx.x * 256 + threadIdx.x;  // over float4s
    float4 v = ((const float4*)x)[gid];
    ushort4 o0, o1;
    split2s(v.x, o0.x, o1.x);
    split2s(v.y, o0.y, o1.y);
    split2s(v.z, o0.z, o1.z);
    split2s(v.w, o0.w, o1.w);
    ((ushort4*)g_XA0)[gid] = o0;
    ((ushort4*)g_XA1)[gid] = o1;
}

// ===========================================================================
// Pre-pass 2: transpose + scaled-split W_enc [K, N] -> g_WB0/1 [N, K]
// ===========================================================================
__global__ __launch_bounds__(256)
void split_w_kernel(const float* __restrict__ W, int ybase)
{
    __shared__ float tile[32][33];
    const int kt = blockIdx.x * 32, nt = (blockIdx.y + ybase) * 32;
    const int tid = threadIdx.x;
    const int tr = tid >> 5, tc = tid & 31;
#pragma unroll
    for (int i = 0; i < 4; i++) {
        int kk = tr + i * 8;
        tile[kk][tc] = W[(size_t)(kt + kk) * D_SAE + nt + tc];
    }
    __syncthreads();
    const int nr = tid >> 3;          // 0..31
    const int kc = (tid & 7) * 4;     // 0..28
    ushort4 o0, o1;
    split2s(tile[kc + 0][nr], o0.x, o1.x);
    split2s(tile[kc + 1][nr], o0.y, o1.y);
    split2s(tile[kc + 2][nr], o0.z, o1.z);
    split2s(tile[kc + 3][nr], o0.w, o1.w);
    size_t off = ((size_t)(nt + nr) * D_MODEL + kt + kc) >> 2;  // in ushort4
    ((ushort4*)g_WB0)[off] = o0;
    ((ushort4*)g_WB1)[off] = o1;
}

// ===========================================================================
// Encode GEMM via mma.sync fp16 (legacy HMMA; tcgen05 blocked by the
// harness's compute_103 virtual arch).
//
// pre = x @ W_enc + b_enc, scaled fp16x2 splits, 3 products:
//   MAIN acc: x0*w0 (chunk-folded every K=128 into smem-resident 'sum')
//   CORR acc: x1s*w0 + x0*w1s (scaled 2^11; one 2^-11 multiply at epilogue)
// PER-OUTPUT ARITHMETIC ORDER IS BIT-IDENTICAL TO THE PASSING R16 KERNEL
// (rel_err 4.613065e-07): same k order, same product order, same fold
// boundaries, same epilogue. Only the warp<->output mapping changed.
//
// R16 ncu: tensor=51%, occ=12.5% (255 regs -> 1 CTA/SM), issue=23.5%.
// R17 occupancy fix: CTA tile 128x64, warp tile m32xn32 (acc+corr = 64
// regs), 'sum' fold state in smem (conflict-free [j][tid] layout) ->
// ~105 regs, __launch_bounds__(256,2) -> 2 CTAs/SM = 4 warps/SMSP.
// ===========================================================================
#define BK      32
#define TS      40                     // padded row stride, halves (80 B)
#define TILE_AB (128 * TS * 2)         // 10240 B (A tile: 128 rows)
#define TILE_BB (64 * TS * 2)          // 5120 B  (B tile: 64 rows)
#define STAGE_B (2 * TILE_AB + 2 * TILE_BB)   // 30720 B per stage
#define SUM_B   (32 * 256 * 4)         // 32 KB fold state
#define SMEM_REQ (2 * STAGE_B + SUM_B) // 94208 B per CTA
#define NSLAB   (D_MODEL / BK)         // 64

__device__ __forceinline__ void mma16816(float* d, const uint32_t* a,
                                         const uint32_t* b) {
    asm volatile(
        "mma.sync.aligned.m16n8k16.row.col.f32.f16.f16.f32 "
        "{%0,%1,%2,%3}, {%4,%5,%6,%7}, {%8,%9}, {%0,%1,%2,%3};"
        : "+f"(d[0]), "+f"(d[1]), "+f"(d[2]), "+f"(d[3])
        : "r"(a[0]), "r"(a[1]), "r"(a[2]), "r"(a[3]), "r"(b[0]), "r"(b[1]));
}

__global__ __launch_bounds__(256, 2)
void encode_gemm_mma(const float* __restrict__ bias, float* __restrict__ C)
{
    extern __shared__ char smem[];
    const uint32_t sbase = smem_u32(smem);
    float* ssum = (float*)(smem + 2 * STAGE_B);   // [32][256] fold state
    const int tid  = threadIdx.x, wid = tid >> 5, lane = tid & 31;
    const int mtile = blockIdx.x, ntile = blockIdx.y;

    const __half* srcA[2] = {
        g_XA0 + (size_t)mtile * 128 * D_MODEL,
        g_XA1 + (size_t)mtile * 128 * D_MODEL };
    const __half* srcB[2] = {
        g_WB0 + (size_t)ntile * 64 * D_MODEL,
        g_WB1 + (size_t)ntile * 64 * D_MODEL };

    // zero fold state (per-thread private slots; no sync needed)
#pragma unroll
    for (int j = 0; j < 32; j++) ssum[j * 256 + tid] = 0.f;

    // stage one K-slab: A0,A1 (128rx64B) + B0,B1 (64rx64B) = 1536 uint4
    auto issue_slab = [&](int t) {
        const uint32_t dstbase = sbase + (uint32_t)(t & 1) * STAGE_B;
        const size_t ks = (size_t)t * BK;
#pragma unroll
        for (int u = 0; u < 6; u++) {
            const int op = u * 256 + tid;       // 0..1535
            uint32_t d; const __half* s;
            if (u < 4) {                        // A tiles: ops 0..1023
                const int tl = op >> 9, inner = op & 511;
                const int r = inner >> 2, seg = inner & 3;
                s = srcA[tl] + (size_t)r * D_MODEL + ks + seg * 8;
                d = dstbase + tl * TILE_AB + r * (TS * 2) + seg * 16;
            } else {                            // B tiles: ops 1024..1535
                const int idx = op - 1024;
                const int tl = idx >> 8, inner = idx & 255;
                const int r = inner >> 2, seg = inner & 3;
                s = srcB[tl] + (size_t)r * D_MODEL + ks + seg * 8;
                d = dstbase + 2 * TILE_AB + tl * TILE_BB + r * (TS * 2) + seg * 16;
            }
            asm volatile("cp.async.cg.shared.global [%0], [%1], 16;"
                         :: "r"(d), "l"(s) : "memory");
        }
        asm volatile("cp.async.commit_group;" ::: "memory");
    };

    float acc[2][4][4], corr[2][4][4];
#pragma unroll
    for (int mi = 0; mi < 2; mi++)
#pragma unroll
        for (int nt = 0; nt < 4; nt++)
#pragma unroll
            for (int q = 0; q < 4; q++) {
                acc[mi][nt][q] = 0.f; corr[mi][nt][q] = 0.f;
            }

    const int wm = (wid & 3) * 32;     // warp M offset (4 warps)
    const int wn = (wid >> 2) * 32;    // warp N offset (2 warps)
    const int lrow = lane & 15, lcol = lane >> 4;

    issue_slab(0);

    for (int t = 0; t < NSLAB; t++) {
        if (t + 1 < NSLAB) {
            issue_slab(t + 1);
            asm volatile("cp.async.wait_group 1;" ::: "memory");
        } else {
            asm volatile("cp.async.wait_group 0;" ::: "memory");
        }
        __syncthreads();

        const uint32_t sb = sbase + (uint32_t)(t & 1) * STAGE_B;
#pragma unroll
        for (int kstep = 0; kstep < 2; kstep++) {
            // A fragments for both splits (m32 x k16 each)
            uint32_t a[2][2][4];
#pragma unroll
            for (int ap = 0; ap < 2; ap++)
#pragma unroll
                for (int mi = 0; mi < 2; mi++) {
                    const uint32_t addr = sb + ap * TILE_AB +
                        (wm + mi * 16 + lrow) * (TS * 2) + kstep * 32 + lcol * 16;
                    asm volatile(
                        "ldmatrix.sync.aligned.m8n8.x4.shared.b16 {%0,%1,%2,%3}, [%4];"
                        : "=r"(a[ap][mi][0]), "=r"(a[ap][mi][1]),
                          "=r"(a[ap][mi][2]), "=r"(a[ap][mi][3])
                        : "r"(addr));
                }
            // products in fixed order: (a0,b0)->MAIN; (a1,b0),(a0,b1)->CORR
#pragma unroll
            for (int bp = 0; bp < 2; bp++) {
                uint32_t bf[4][2];
#pragma unroll
                for (int nb = 0; nb < 2; nb++) {   // two 16-row B groups
                    uint32_t r0, r1, r2, r3;
                    const uint32_t addr = sb + 2 * TILE_AB + bp * TILE_BB +
                        (wn + nb * 16 + lrow) * (TS * 2) + kstep * 32 + lcol * 16;
                    asm volatile(
                        "ldmatrix.sync.aligned.m8n8.x4.shared.b16 {%0,%1,%2,%3}, [%4];"
                        : "=r"(r0), "=r"(r1), "=r"(r2), "=r"(r3)
                        : "r"(addr));
                    bf[2 * nb][0] = r0;  bf[2 * nb][1] = r2;
                    bf[2 * nb + 1][0] = r1;  bf[2 * nb + 1][1] = r3;
                }
#pragma unroll
                for (int ap = 0; ap < 2; ap++) {
                    if (ap + bp <= 1) {   // 3 products: i+j<=1
                        const bool main = (ap == 0) && (bp == 0);
#pragma unroll
                        for (int mi = 0; mi < 2; mi++)
#pragma unroll
                            for (int nt = 0; nt < 4; nt++)
                                mma16816(main ? acc[mi][nt] : corr[mi][nt],
                                         a[ap][mi], bf[nt]);
                    }
                }
            }
        }
        __syncthreads();

        if ((t & 3) == 3) {   // MAIN chunk fold every K=128 (smem state)
#pragma unroll
            for (int mi = 0; mi < 2; mi++)
#pragma unroll
                for (int nt = 0; nt < 4; nt++)
#pragma unroll
                    for (int q = 0; q < 4; q++) {
                        const int j = (mi * 4 + nt) * 4 + q;
                        ssum[j * 256 + tid] =
                            __fadd_rn(ssum[j * 256 + tid], acc[mi][nt][q]);
                        acc[mi][nt][q] = 0.f;
                    }
        }
    }

    // epilogue: pre = (sum + corr*2^-11) + bias   (deterministic order)
#pragma unroll
    for (int mi = 0; mi < 2; mi++)
#pragma unroll
        for (int nt = 0; nt < 4; nt++) {
            const int row = mtile * 128 + wm + mi * 16 + (lane >> 2);
            const int col = ntile * 64 + wn + nt * 8 + (lane & 3) * 2;
            const float b0 = bias[col], b1 = bias[col + 1];
            const int jb = (mi * 4 + nt) * 4;
            float2 v0, v1;
            v0.x = __fadd_rn(__fadd_rn(ssum[(jb + 0) * 256 + tid],
                     __fmul_rn(corr[mi][nt][0], RSCALE_INV)), b0);
            v0.y = __fadd_rn(__fadd_rn(ssum[(jb + 1) * 256 + tid],
                     __fmul_rn(corr[mi][nt][1], RSCALE_INV)), b1);
            v1.x = __fadd_rn(__fadd_rn(ssum[(jb + 2) * 256 + tid],
                     __fmul_rn(corr[mi][nt][2], RSCALE_INV)), b0);
            v1.y = __fadd_rn(__fadd_rn(ssum[(jb + 3) * 256 + tid],
                     __fmul_rn(corr[mi][nt][3], RSCALE_INV)), b1);
            *(float2*)(C + (size_t)row * D_SAE + col)       = v0;
            *(float2*)(C + (size_t)(row + 8) * D_SAE + col) = v1;
        }
}

// ============================================================================
// Top-64 of relu(pre) — exact selection (values desc, ties lowest-index,
// matches jax.lax.top_k). 11-bit histogram + suffix scan + candidate
// collection + O(c^2) rank selection. (Unchanged from passing R13.)
// ============================================================================
#define NBIN 2048
#define CAND 2048

__global__ __launch_bounds__(256)
void topk_kernel(const float* __restrict__ pre, float* __restrict__ z)
{
    __shared__ int   hist[2][NBIN];
    __shared__ int   s_scan[256];
    __shared__ float cv[CAND];
    __shared__ int   ci[CAND];
    __shared__ int   s_cnt, s_B, s_K;

    const int tid = threadIdx.x;           // 256 threads
    const int n   = blockIdx.x;
    const float* row = pre + (size_t)n * D_SAE;
    const int h = (tid >> 5) & 1;

    for (int i = tid; i < NBIN; i += 256) { hist[0][i] = 0; hist[1][i] = 0; }
    if (tid < KTOP) { g_vals[n * KTOP + tid] = 0.f; g_idx[n * KTOP + tid] = 0; }
    if (tid == 0) s_cnt = 0;
    __syncthreads();

    for (int i = tid; i < D_SAE / 4; i += 256) {
        float4 v = ((const float4*)row)[i];
        if (v.x > 0.f) atomicAdd(&hist[h][__float_as_uint(v.x) >> 20], 1);
        if (v.y > 0.f) atomicAdd(&hist[h][__float_as_uint(v.y) >> 20], 1);
        if (v.z > 0.f) atomicAdd(&hist[h][__float_as_uint(v.z) >> 20], 1);
        if (v.w > 0.f) atomicAdd(&hist[h][__float_as_uint(v.w) >> 20], 1);
    }
    __syncthreads();

    int tsum = 0;
#pragma unroll
    for (int b = 0; b < 8; b++) {
        const int bb = tid * 8 + b;
        const int c = hist[0][bb] + hist[1][bb];
        hist[0][bb] = c;
        tsum += c;
    }
    s_scan[tid] = tsum;
    __syncthreads();

    for (int off = 1; off < 256; off <<= 1) {
        int v = (tid + off < 256) ? s_scan[tid + off] : 0;
        __syncthreads();
        s_scan[tid] += v;
        __syncthreads();
    }
    const int total = s_scan[0];

    if (total <= KTOP) {
        if (tid == 0) { s_B = 0; s_K = total; }
    } else {
        const int above = (tid < 255) ? s_scan[tid + 1] : 0;
        if (s_scan[tid] >= KTOP && above < KTOP) {
            int cum = above, B = tid * 8;
#pragma unroll
            for (int b = 7; b >= 0; b--) {
                cum += hist[0][tid * 8 + b];
                if (cum >= KTOP) { B = tid * 8 + b; break; }
            }
            s_B = B; s_K = KTOP;
        }
    }
    __syncthreads();
    const unsigned B = (unsigned)s_B;
    const int Ksel = s_K;

    for (int i = tid; i < D_SAE / 4; i += 256) {
        float4 v = ((const float4*)row)[i];
        const int base = 4 * i;
        if (v.x > 0.f && (__float_as_uint(v.x) >> 20) >= B) {
            int p = atomicAdd(&s_cnt, 1);
            if (p < CAND) { cv[p] = v.x; ci[p] = base; }
        }
        if (v.y > 0.f && (__float_as_uint(v.y) >> 20) >= B) {
            int p = atomicAdd(&s_cnt, 1);
            if (p < CAND) { cv[p] = v.y; ci[p] = base + 1; }
        }
        if (v.z > 0.f && (__float_as_uint(v.z) >> 20) >= B) {
            int p = atomicAdd(&s_cnt, 1);
            if (p < CAND) { cv[p] = v.z; ci[p] = base + 2; }
        }
        if (v.w > 0.f && (__float_as_uint(v.w) >> 20) >= B) {
            int p = atomicAdd(&s_cnt, 1);
            if (p < CAND) { cv[p] = v.w; ci[p] = base + 3; }
        }
    }
    __syncthreads();
    const int c = min(s_cnt, CAND);

    for (int p = tid; p < c; p += 256) {
        const float vp = cv[p];
        const int   ip = ci[p];
        int rank = 0;
        for (int q = 0; q < c; q++) {
            const float vq = cv[q];
            rank += (vq > vp) || (vq == vp && ci[q] < ip);
        }
        if (rank < Ksel) {
            g_vals[n * KTOP + rank] = vp;
            g_idx [n * KTOP + rank] = ip;
            z[(size_t)n * D_SAE + ip] = vp;
        }
    }
}

// ============================================================================
// Sparse decode  x_hat[n] = sum_k v_k * W_dec[idx_k, :] + b_dec
// ============================================================================
__global__ __launch_bounds__(256)
void decode_kernel(const float* __restrict__ Wdec,
                   const float* __restrict__ bdec,
                   float* __restrict__ xhat)
{
    __shared__ float sv[KTOP];
    __shared__ int   si[KTOP];
    const int n = blockIdx.x, tid = threadIdx.x;
    if (tid < KTOP) {
        sv[tid] = g_vals[n * KTOP + tid];
        si[tid] = g_idx [n * KTOP + tid];
    }
    __syncthreads();

    float acc[8];
#pragma unroll
    for (int j = 0; j < 8; j++) acc[j] = bdec[tid + j * 256];

    for (int k = 0; k < KTOP; k++) {
        float v = sv[k];
        const float* wr = Wdec + (size_t)si[k] * D_MODEL;
#pragma unroll
        for (int j = 0; j < 8; j++)
            acc[j] = fmaf(v, wr[tid + j * 256], acc[j]);
    }

    float* orow = xhat + (size_t)n * D_MODEL;
#pragma unroll
    for (int j = 0; j < 8; j++) orow[tid + j * 256] = acc[j];
}

// ============================================================================
// Launch: out = [x_hat | z | pre], all fp32. Graph-capturable.
// ============================================================================
extern "C" void kernel_launch(void* const* d_in, const int* in_sizes, int n_in,
                              void* d_out, int out_size)
{
    (void)in_sizes; (void)n_in; (void)out_size;
    const float* x     = (const float*)d_in[0];
    const float* W_enc = (const float*)d_in[1];
    const float* b_enc = (const float*)d_in[2];
    const float* W_dec = (const float*)d_in[3];
    const float* b_dec = (const float*)d_in[4];

    float* out  = (float*)d_out;
    float* xhat = out;
    float* z    = out + (size_t)N_TOK * D_MODEL;
    float* pre  = z   + (size_t)N_TOK * D_SAE;

    cudaMemsetAsync(z, 0, (size_t)N_TOK * D_SAE * sizeof(float), 0);

    // pre-pass: scaled fp16x2 splits
    split_x_kernel<<<(N_TOK * D_MODEL / 4) / 256, 256>>>(x);
    split_w_kernel<<<dim3(D_MODEL / 32, D_SAE / 64), 256>>>(W_enc, 0);
    split_w_kernel<<<dim3(D_MODEL / 32, D_SAE / 64), 256>>>(W_enc, D_SAE / 64);

    // fp16x2 mma.sync encode GEMM, CTA 128x64, 2 CTAs/SM
    // (grid x = M-tiles: each wave keeps A L2-resident, streams B once)
    cudaFuncSetAttribute(encode_gemm_mma,
                         cudaFuncAttributeMaxDynamicSharedMemorySize, SMEM_REQ);
    encode_gemm_mma<<<dim3(N_TOK / 128, D_SAE / 64), 256, SMEM_REQ>>>(b_enc, pre);

    topk_kernel<<<N_TOK, 256>>>(pre, z);

    decode_kernel<<<N_TOK, 256>>>(W_dec, b_dec, xhat);
}